// round 1
// baseline (speedup 1.0000x reference)
#include <cuda_runtime.h>
#include <cuda_bf16.h>
#include <cstdint>

#define B_ 4096
#define N_ 32768
#define D_ 1024
#define BM 128
#define BN 128
#define BK 64
#define SSTR 72            // smem row stride in bf16 elems (144B, mult of 16B, conflict-free)
#define EPSTR 132          // epilogue smem row stride in floats
#define NBLK (N_/BN)       // 256 n-blocks per row (sum/sumsq partials)
#define NSUB (N_/16)       // 2048 16-key sub-blocks per row (top-1 candidates)
#define MARGIN 0.002f

// ------------------------- scratch (no allocations allowed) -------------------------
__device__ float         g_qn[(size_t)B_*D_];     // normalized Q fp32 (for refinement)
__device__ __nv_bfloat16 g_qb[(size_t)B_*D_];     // normalized Q bf16
__device__ __nv_bfloat16 g_kb[(size_t)N_*D_];     // normalized K bf16
__device__ float         g_kinv[N_];              // 1/||k||
__device__ float2        g_part[(size_t)B_*NBLK]; // per (row, nblock): (sum, sumsq)
__device__ float         g_topv[(size_t)B_*NSUB]; // per (row, subblock): approx max sim
__device__ int           g_topi[(size_t)B_*NSUB]; // per (row, subblock): its key index
__device__ float         g_var[B_];

// ------------------------- normalize -------------------------
__global__ void norm_rows_q(const float* __restrict__ x) {
    int row = blockIdx.x, tid = threadIdx.x;
    const float4* xp = (const float4*)(x + (size_t)row * D_);
    float4 a = xp[tid];
    float ss = a.x*a.x + a.y*a.y + a.z*a.z + a.w*a.w;
    __shared__ float sh[256];
    sh[tid] = ss; __syncthreads();
    for (int s = 128; s > 0; s >>= 1) { if (tid < s) sh[tid] += sh[tid+s]; __syncthreads(); }
    float inv = 1.0f / fmaxf(sqrtf(sh[0]), 1e-12f);
    float4 o; o.x = a.x*inv; o.y = a.y*inv; o.z = a.z*inv; o.w = a.w*inv;
    ((float4*)(g_qn + (size_t)row * D_))[tid] = o;
    __nv_bfloat162 h0 = __floats2bfloat162_rn(o.x, o.y);
    __nv_bfloat162 h1 = __floats2bfloat162_rn(o.z, o.w);
    uint2 pk; pk.x = *(uint32_t*)&h0; pk.y = *(uint32_t*)&h1;
    ((uint2*)(g_qb + (size_t)row * D_))[tid] = pk;
}

__global__ void norm_rows_k(const float* __restrict__ x) {
    int row = blockIdx.x, tid = threadIdx.x;
    const float4* xp = (const float4*)(x + (size_t)row * D_);
    float4 a = xp[tid];
    float ss = a.x*a.x + a.y*a.y + a.z*a.z + a.w*a.w;
    __shared__ float sh[256];
    sh[tid] = ss; __syncthreads();
    for (int s = 128; s > 0; s >>= 1) { if (tid < s) sh[tid] += sh[tid+s]; __syncthreads(); }
    float inv = 1.0f / fmaxf(sqrtf(sh[0]), 1e-12f);
    if (tid == 0) g_kinv[row] = inv;
    float4 o; o.x = a.x*inv; o.y = a.y*inv; o.z = a.z*inv; o.w = a.w*inv;
    __nv_bfloat162 h0 = __floats2bfloat162_rn(o.x, o.y);
    __nv_bfloat162 h1 = __floats2bfloat162_rn(o.z, o.w);
    uint2 pk; pk.x = *(uint32_t*)&h0; pk.y = *(uint32_t*)&h1;
    ((uint2*)(g_kb + (size_t)row * D_))[tid] = pk;
}

// ------------------------- GEMM (bf16 mma.sync) with fused stats epilogue -------------------------
__device__ __forceinline__ uint32_t cvta_s(const void* p) {
    return (uint32_t)__cvta_generic_to_shared(p);
}
__device__ __forceinline__ void ldsm4(uint32_t& r0, uint32_t& r1, uint32_t& r2, uint32_t& r3, uint32_t a) {
    asm volatile("ldmatrix.sync.aligned.m8n8.x4.shared.b16 {%0,%1,%2,%3},[%4];\n"
        : "=r"(r0), "=r"(r1), "=r"(r2), "=r"(r3) : "r"(a));
}
__device__ __forceinline__ void mma16816(float* c, const uint32_t* a, const uint32_t* b) {
    asm volatile("mma.sync.aligned.m16n8k16.row.col.f32.bf16.bf16.f32 "
        "{%0,%1,%2,%3},{%4,%5,%6,%7},{%8,%9},{%0,%1,%2,%3};\n"
        : "+f"(c[0]), "+f"(c[1]), "+f"(c[2]), "+f"(c[3])
        : "r"(a[0]), "r"(a[1]), "r"(a[2]), "r"(a[3]), "r"(b[0]), "r"(b[1]));
}

__global__ __launch_bounds__(256, 2) void sim_gemm() {
    __shared__ __align__(16) unsigned char smraw[(BM + BN) * SSTR * 2];
    __nv_bfloat16* sA = (__nv_bfloat16*)smraw;
    __nv_bfloat16* sB = sA + BM * SSTR;
    float* ep = (float*)smraw;   // epilogue reuse: 64 x 132 floats = 33792B <= 36864B

    const int tid = threadIdx.x;
    const int lane = tid & 31, warp = tid >> 5;
    const int wm = (warp >> 2) * 64;      // 2 warp-rows of 64
    const int wn = (warp & 3) * 32;       // 4 warp-cols of 32
    const int m0 = blockIdx.x * BM;       // m fastest -> Q chunk reuse in L2
    const int n0 = blockIdx.y * BN;

    float acc[4][4][4];
    #pragma unroll
    for (int i = 0; i < 4; i++)
        #pragma unroll
        for (int j = 0; j < 4; j++)
            #pragma unroll
            for (int k = 0; k < 4; k++) acc[i][j][k] = 0.f;

    const int lr = tid >> 3;   // 0..31 (row group for loads)
    const int lc = tid & 7;    // 16B chunk column

    for (int k0 = 0; k0 < D_; k0 += BK) {
        #pragma unroll
        for (int it = 0; it < 4; ++it) {
            int r = lr + it * 32;
            *(uint4*)(sA + r * SSTR + lc * 8) =
                *(const uint4*)(g_qb + (size_t)(m0 + r) * D_ + k0 + lc * 8);
            *(uint4*)(sB + r * SSTR + lc * 8) =
                *(const uint4*)(g_kb + (size_t)(n0 + r) * D_ + k0 + lc * 8);
        }
        __syncthreads();
        #pragma unroll
        for (int kk = 0; kk < BK; kk += 16) {
            uint32_t af[4][4], bf[4][2];
            int rsel = lane & 15, csel = kk + ((lane >> 4) << 3);
            #pragma unroll
            for (int mi = 0; mi < 4; ++mi) {
                uint32_t ad = cvta_s(sA + (wm + mi * 16 + rsel) * SSTR + csel);
                ldsm4(af[mi][0], af[mi][1], af[mi][2], af[mi][3], ad);
            }
            #pragma unroll
            for (int nh = 0; nh < 2; ++nh) {
                uint32_t r0, r1, r2, r3;
                uint32_t ad = cvta_s(sB + (wn + nh * 16 + rsel) * SSTR + csel);
                ldsm4(r0, r1, r2, r3, ad);
                bf[nh*2+0][0] = r0; bf[nh*2+0][1] = r2;
                bf[nh*2+1][0] = r1; bf[nh*2+1][1] = r3;
            }
            #pragma unroll
            for (int mi = 0; mi < 4; ++mi)
                #pragma unroll
                for (int ni = 0; ni < 4; ++ni)
                    mma16816(acc[mi][ni], af[mi], bf[ni]);
        }
        __syncthreads();
    }

    // Fused epilogue: two phases of 64 rows through smem
    #pragma unroll 1
    for (int ph = 0; ph < 2; ++ph) {
        if ((warp >> 2) == ph) {
            #pragma unroll
            for (int mi = 0; mi < 4; ++mi)
                #pragma unroll
                for (int ni = 0; ni < 4; ++ni) {
                    int r = mi * 16 + (lane >> 2);
                    int c = wn + ni * 8 + ((lane & 3) << 1);
                    ep[r * EPSTR + c]           = acc[mi][ni][0];
                    ep[r * EPSTR + c + 1]       = acc[mi][ni][1];
                    ep[(r + 8) * EPSTR + c]     = acc[mi][ni][2];
                    ep[(r + 8) * EPSTR + c + 1] = acc[mi][ni][3];
                }
        }
        __syncthreads();
        {
            int r = tid >> 2, t = tid & 3;         // 4 threads per row, 32 cols each
            const float* rowp = ep + r * EPSTR + t * 32;
            int grow = m0 + ph * 64 + r;
            float s = 0.f, q2 = 0.f;
            #pragma unroll
            for (int h = 0; h < 2; ++h) {          // two 16-key sub-blocks
                float mv = -1e30f; int mx = 0;
                #pragma unroll
                for (int c = 0; c < 16; ++c) {
                    float v = rowp[h * 16 + c];
                    s += v; q2 += v * v;
                    if (v > mv) { mv = v; mx = c; }   // strict > -> smallest index on tie
                }
                int sb = blockIdx.y * 8 + t * 2 + h;
                g_topv[(size_t)grow * NSUB + sb] = mv;
                g_topi[(size_t)grow * NSUB + sb] = n0 + t * 32 + h * 16 + mx;
            }
            s  += __shfl_down_sync(0xffffffffu, s,  2, 4);
            q2 += __shfl_down_sync(0xffffffffu, q2, 2, 4);
            s  += __shfl_down_sync(0xffffffffu, s,  1, 4);
            q2 += __shfl_down_sync(0xffffffffu, q2, 1, 4);
            if (t == 0)
                g_part[(size_t)grow * NBLK + blockIdx.y] = make_float2(s, q2);
        }
        __syncthreads();
    }
}

// ------------------------- finalize: var + exact-fp32 argmax refinement + gather -------------------------
__global__ void finalize_rows(const float* __restrict__ keys,
                              const float* __restrict__ values,
                              float* __restrict__ out) {
    int row = blockIdx.x, tid = threadIdx.x;
    __shared__ float sv[256]; __shared__ int si[256];
    __shared__ float s1[256], s2[256];
    __shared__ int clist[64]; __shared__ int ccnt;

    float2 p = g_part[(size_t)row * NBLK + tid];
    float tv[8];
    float lm = -1e30f;
    #pragma unroll
    for (int k = 0; k < 8; ++k) {
        tv[k] = g_topv[(size_t)row * NSUB + tid + k * 256];
        lm = fmaxf(lm, tv[k]);
    }
    sv[tid] = lm; s1[tid] = p.x; s2[tid] = p.y;
    if (tid == 0) ccnt = 0;
    __syncthreads();
    for (int s = 128; s > 0; s >>= 1) {
        if (tid < s) {
            s1[tid] += s1[tid + s];
            s2[tid] += s2[tid + s];
            sv[tid] = fmaxf(sv[tid], sv[tid + s]);
        }
        __syncthreads();
    }
    float M = sv[0], sum = s1[0], sumsq = s2[0];
    __syncthreads();

    float thr = M - MARGIN;
    #pragma unroll
    for (int k = 0; k < 8; ++k) {
        if (tv[k] >= thr) {
            int pos = atomicAdd(&ccnt, 1);
            if (pos < 64) clist[pos] = tid + k * 256;
        }
    }
    __syncthreads();
    int nc = min(ccnt, 64);

    // exact fp32 dot for each candidate sub-block (16 keys, 16 threads/key)
    int kg = tid >> 4;       // key index within sub-block
    int lig = tid & 15;      // lane within key group
    float bv = -1e30f; int bi = 0x7fffffff;
    const float4* qp = (const float4*)(g_qn + (size_t)row * D_) + lig * 16;
    for (int ci = 0; ci < nc; ++ci) {
        int n = clist[ci] * 16 + kg;
        const float4* kp = (const float4*)(keys + (size_t)n * D_) + lig * 16;
        float a0 = 0.f;
        #pragma unroll
        for (int j = 0; j < 16; ++j) {
            float4 qa = qp[j], kb = kp[j];
            a0 += qa.x*kb.x + qa.y*kb.y + qa.z*kb.z + qa.w*kb.w;
        }
        a0 += __shfl_xor_sync(0xffffffffu, a0, 8);
        a0 += __shfl_xor_sync(0xffffffffu, a0, 4);
        a0 += __shfl_xor_sync(0xffffffffu, a0, 2);
        a0 += __shfl_xor_sync(0xffffffffu, a0, 1);
        if (lig == 0) {
            float s = a0 * g_kinv[n];
            if (s > bv || (s == bv && n < bi)) { bv = s; bi = n; }
        }
    }
    sv[tid] = (lig == 0) ? bv : -1e30f;
    si[tid] = (lig == 0) ? bi : 0x7fffffff;
    __syncthreads();
    for (int s = 128; s > 0; s >>= 1) {
        if (tid < s) {
            if (sv[tid + s] > sv[tid] ||
                (sv[tid + s] == sv[tid] && si[tid + s] < si[tid])) {
                sv[tid] = sv[tid + s]; si[tid] = si[tid + s];
            }
        }
        __syncthreads();
    }
    int best = si[0];

    const float4* vp = (const float4*)(values + (size_t)best * D_);
    float4* op = (float4*)(out + (size_t)row * D_);
    op[tid] = vp[tid];

    if (tid == 0)
        g_var[row] = (sumsq - sum * sum * (1.0f / N_)) * (1.0f / (N_ - 1));
}

__global__ void var_mean(float* __restrict__ out, int out_size) {
    __shared__ float sh[256];
    int tid = threadIdx.x;
    float a = 0.f;
    for (int i = tid; i < B_; i += 256) a += g_var[i];
    sh[tid] = a; __syncthreads();
    for (int s = 128; s > 0; s >>= 1) { if (tid < s) sh[tid] += sh[tid + s]; __syncthreads(); }
    if (tid == 0) {
        long long base = (long long)B_ * D_;
        if (out_size > base) out[base] = sh[0] * (1.0f / B_);
    }
}

// ------------------------- launch -------------------------
extern "C" void kernel_launch(void* const* d_in, const int* in_sizes, int n_in,
                              void* d_out, int out_size) {
    const float* q = (const float*)d_in[0];
    const float* k = (const float*)d_in[1];
    const float* v = (const float*)d_in[2];
    float* out = (float*)d_out;

    norm_rows_q<<<B_, 256>>>(q);
    norm_rows_k<<<N_, 256>>>(k);
    dim3 g(B_ / BM, NBLK);   // m fastest within a wave -> Q reuse through L2
    sim_gemm<<<g, 256>>>();
    finalize_rows<<<B_, 256>>>(k, v, out);
    var_mean<<<1, 256>>>(out, out_size);
}

// round 4
// speedup vs baseline: 1.2564x; 1.2564x over previous
#include <cuda_runtime.h>
#include <cuda_bf16.h>
#include <cstdint>

#define B_ 4096
#define N_ 32768
#define D_ 1024
#define BM 128
#define BN 128
#define BK 64
#define NSTAGE 3
#define KSLABS (D_/BK)          // 16
#define SLAB 16384              // 128 rows * 128B (one operand, one k-slab)
#define STAGE_BYTES (2*SLAB)    // A + B
#define NBLK (N_/BN)            // 256 n-blocks per row
#define NSUB (N_/16)            // 2048 16-key sub-blocks per row
#define EPSTR 132
#define MARGIN 0.002f

// ------------------------- scratch (no allocations allowed) -------------------------
__device__ float         g_qn[(size_t)B_*D_];     // normalized Q fp32 (refinement)
__device__ unsigned char g_qsw[(size_t)B_*D_*2];  // Q bf16, slab-contiguous SW128 layout
__device__ unsigned char g_ksw[(size_t)N_*D_*2];  // K bf16, slab-contiguous SW128 layout
__device__ float         g_kinv[N_];              // 1/||k||
__device__ float2        g_part[(size_t)B_*NBLK]; // per (row, nblock): (sum, sumsq)
__device__ float         g_topv[(size_t)B_*NSUB]; // per (row, subblock): approx max sim
__device__ float         g_var[B_];

// ------------------------- helpers -------------------------
__device__ __forceinline__ uint32_t cvta_s(const void* p) {
    return (uint32_t)__cvta_generic_to_shared(p);
}
__device__ __forceinline__ void cp_async16(uint32_t dst, const void* src) {
    asm volatile("cp.async.cg.shared.global [%0], [%1], 16;\n" :: "r"(dst), "l"(src));
}
__device__ __forceinline__ void cp_commit() {
    asm volatile("cp.async.commit_group;\n" ::: "memory");
}
template <int NN> __device__ __forceinline__ void cp_wait() {
    asm volatile("cp.async.wait_group %0;\n" :: "n"(NN) : "memory");
}
__device__ __forceinline__ void ldsm4(uint32_t& r0, uint32_t& r1, uint32_t& r2, uint32_t& r3, uint32_t a) {
    asm volatile("ldmatrix.sync.aligned.m8n8.x4.shared.b16 {%0,%1,%2,%3},[%4];\n"
        : "=r"(r0), "=r"(r1), "=r"(r2), "=r"(r3) : "r"(a));
}
__device__ __forceinline__ void mma16816(float* c, const uint32_t* a, const uint32_t* b) {
    asm volatile("mma.sync.aligned.m16n8k16.row.col.f32.bf16.bf16.f32 "
        "{%0,%1,%2,%3},{%4,%5,%6,%7},{%8,%9},{%0,%1,%2,%3};\n"
        : "+f"(c[0]), "+f"(c[1]), "+f"(c[2]), "+f"(c[3])
        : "r"(a[0]), "r"(a[1]), "r"(a[2]), "r"(a[3]), "r"(b[0]), "r"(b[1]));
}
// byte offset of (row, colByte) inside a 128x128B SW128 tile
__device__ __forceinline__ uint32_t swz(uint32_t r, uint32_t cByte) {
    return r * 128u + (cByte ^ ((r & 7u) << 4));
}

// ------------------------- normalize (writes SW128 slab-contiguous layout) -------------------------
__global__ void norm_rows_q(const float* __restrict__ x) {
    int row = blockIdx.x, tid = threadIdx.x;
    const float4* xp = (const float4*)(x + (size_t)row * D_);
    float4 a = xp[tid];
    float ss = a.x*a.x + a.y*a.y + a.z*a.z + a.w*a.w;
    __shared__ float sh[256];
    sh[tid] = ss; __syncthreads();
    for (int s = 128; s > 0; s >>= 1) { if (tid < s) sh[tid] += sh[tid+s]; __syncthreads(); }
    float inv = 1.0f / fmaxf(sqrtf(sh[0]), 1e-12f);
    float4 o; o.x = a.x*inv; o.y = a.y*inv; o.z = a.z*inv; o.w = a.w*inv;
    ((float4*)(g_qn + (size_t)row * D_))[tid] = o;
    __nv_bfloat162 h0 = __floats2bfloat162_rn(o.x, o.y);
    __nv_bfloat162 h1 = __floats2bfloat162_rn(o.z, o.w);
    uint2 pk; pk.x = *(uint32_t*)&h0; pk.y = *(uint32_t*)&h1;
    int mt = row >> 7, r_in = row & 127;
    int kslab = tid >> 4;                     // 16 threads (64 elems) per k-slab
    uint32_t cByte = (uint32_t)((tid & 15) * 8);
    uint32_t off = swz((uint32_t)r_in, cByte);
    *(uint2*)(g_qsw + (size_t)(mt * KSLABS + kslab) * SLAB + off) = pk;
}

__global__ void norm_rows_k(const float* __restrict__ x) {
    int row = blockIdx.x, tid = threadIdx.x;
    const float4* xp = (const float4*)(x + (size_t)row * D_);
    float4 a = xp[tid];
    float ss = a.x*a.x + a.y*a.y + a.z*a.z + a.w*a.w;
    __shared__ float sh[256];
    sh[tid] = ss; __syncthreads();
    for (int s = 128; s > 0; s >>= 1) { if (tid < s) sh[tid] += sh[tid+s]; __syncthreads(); }
    float inv = 1.0f / fmaxf(sqrtf(sh[0]), 1e-12f);
    if (tid == 0) g_kinv[row] = inv;
    float4 o; o.x = a.x*inv; o.y = a.y*inv; o.z = a.z*inv; o.w = a.w*inv;
    __nv_bfloat162 h0 = __floats2bfloat162_rn(o.x, o.y);
    __nv_bfloat162 h1 = __floats2bfloat162_rn(o.z, o.w);
    uint2 pk; pk.x = *(uint32_t*)&h0; pk.y = *(uint32_t*)&h1;
    int nt = row >> 7, r_in = row & 127;
    int kslab = tid >> 4;
    uint32_t cByte = (uint32_t)((tid & 15) * 8);
    uint32_t off = swz((uint32_t)r_in, cByte);
    *(uint2*)(g_ksw + (size_t)(nt * KSLABS + kslab) * SLAB + off) = pk;
}

// ------------------------- GEMM: mma.sync + cp.async 3-stage pipeline -------------------------
__global__ __launch_bounds__(256, 2) void sim_gemm() {
    extern __shared__ __align__(16) unsigned char smraw[];   // NSTAGE * 32KB
    float* ep = (float*)smraw;

    const int tid = threadIdx.x;
    const int lane = tid & 31, warp = tid >> 5;
    const int wm = (warp >> 2) * 64;
    const int wn = (warp & 3) * 32;
    const int mt = blockIdx.x;
    const int nt = blockIdx.y;
    const int m0 = mt * BM, n0 = nt * BN;

    const unsigned char* qbase = g_qsw + (size_t)mt * KSLABS * SLAB;
    const unsigned char* kbase = g_ksw + (size_t)nt * KSLABS * SLAB;
    const uint32_t sbase = cvta_s(smraw);

    float acc[4][4][4];
    #pragma unroll
    for (int i = 0; i < 4; i++)
        #pragma unroll
        for (int j = 0; j < 4; j++)
            #pragma unroll
            for (int k = 0; k < 4; k++) acc[i][j][k] = 0.f;

    // prologue: load slabs 0,1 into stages 0,1
    #pragma unroll
    for (int s = 0; s < NSTAGE - 1; ++s) {
        uint32_t st = sbase + s * STAGE_BYTES;
        #pragma unroll
        for (int i = 0; i < 4; ++i) {
            uint32_t o = (uint32_t)(i * 4096 + tid * 16);
            cp_async16(st + o,        qbase + (size_t)s * SLAB + o);
            cp_async16(st + SLAB + o, kbase + (size_t)s * SLAB + o);
        }
        cp_commit();
    }

    const uint32_t rsel = lane & 15;
    const uint32_t cbase = (uint32_t)((lane >> 4) << 4);   // 0 or 16 bytes

    #pragma unroll 1
    for (int t = 0; t < KSLABS; ++t) {
        cp_wait<1>();
        __syncthreads();
        if (t + NSTAGE - 1 < KSLABS) {
            int s2 = (t + NSTAGE - 1) % NSTAGE;
            uint32_t st = sbase + s2 * STAGE_BYTES;
            #pragma unroll
            for (int i = 0; i < 4; ++i) {
                uint32_t o = (uint32_t)(i * 4096 + tid * 16);
                cp_async16(st + o,        qbase + (size_t)(t + NSTAGE - 1) * SLAB + o);
                cp_async16(st + SLAB + o, kbase + (size_t)(t + NSTAGE - 1) * SLAB + o);
            }
        }
        cp_commit();

        uint32_t sA = sbase + (t % NSTAGE) * STAGE_BYTES;
        uint32_t sB = sA + SLAB;
        #pragma unroll
        for (int kk = 0; kk < 4; ++kk) {
            uint32_t cByte = (uint32_t)(kk * 32) + cbase;
            uint32_t af[4][4], bf[4][2];
            #pragma unroll
            for (int mi = 0; mi < 4; ++mi)
                ldsm4(af[mi][0], af[mi][1], af[mi][2], af[mi][3],
                      sA + swz(wm + mi * 16 + rsel, cByte));
            #pragma unroll
            for (int nh = 0; nh < 2; ++nh) {
                uint32_t r0, r1, r2, r3;
                ldsm4(r0, r1, r2, r3, sB + swz(wn + nh * 16 + rsel, cByte));
                bf[nh*2+0][0] = r0; bf[nh*2+0][1] = r2;
                bf[nh*2+1][0] = r1; bf[nh*2+1][1] = r3;
            }
            #pragma unroll
            for (int mi = 0; mi < 4; ++mi)
                #pragma unroll
                for (int ni = 0; ni < 4; ++ni)
                    mma16816(acc[mi][ni], af[mi], bf[ni]);
        }
    }
    __syncthreads();   // all compute done before smem reuse as epilogue buffer

    // epilogue: two phases of 64 rows through smem; fused stats
    #pragma unroll 1
    for (int ph = 0; ph < 2; ++ph) {
        if ((warp >> 2) == ph) {
            #pragma unroll
            for (int mi = 0; mi < 4; ++mi)
                #pragma unroll
                for (int ni = 0; ni < 4; ++ni) {
                    int r = mi * 16 + (lane >> 2);
                    int c = wn + ni * 8 + ((lane & 3) << 1);
                    ep[r * EPSTR + c]           = acc[mi][ni][0];
                    ep[r * EPSTR + c + 1]       = acc[mi][ni][1];
                    ep[(r + 8) * EPSTR + c]     = acc[mi][ni][2];
                    ep[(r + 8) * EPSTR + c + 1] = acc[mi][ni][3];
                }
        }
        __syncthreads();
        {
            int r = tid >> 2, tq = tid & 3;        // 4 threads per row, 32 cols each
            const float* rowp = ep + r * EPSTR + tq * 32;
            int grow = m0 + ph * 64 + r;
            float s = 0.f, q2 = 0.f;
            #pragma unroll
            for (int h = 0; h < 2; ++h) {          // two 16-key sub-blocks
                float mv = -1e30f;
                #pragma unroll
                for (int c = 0; c < 16; ++c) {
                    float v = rowp[h * 16 + c];
                    s += v; q2 += v * v;
                    mv = fmaxf(mv, v);
                }
                g_topv[(size_t)grow * NSUB + nt * 8 + tq * 2 + h] = mv;
            }
            s  += __shfl_down_sync(0xffffffffu, s,  2, 4);
            q2 += __shfl_down_sync(0xffffffffu, q2, 2, 4);
            s  += __shfl_down_sync(0xffffffffu, s,  1, 4);
            q2 += __shfl_down_sync(0xffffffffu, q2, 1, 4);
            if (tq == 0)
                g_part[(size_t)grow * NBLK + nt] = make_float2(s, q2);
        }
        __syncthreads();
    }
}

// ------------------------- finalize: var + exact-fp32 argmax refinement + gather -------------------------
__global__ void finalize_rows(const float* __restrict__ keys,
                              const float* __restrict__ values,
                              float* __restrict__ out) {
    int row = blockIdx.x, tid = threadIdx.x;
    __shared__ float sv[256]; __shared__ int si[256];
    __shared__ float s1[256], s2[256];
    __shared__ int clist[64]; __shared__ int ccnt;

    float2 p = g_part[(size_t)row * NBLK + tid];
    float tv[8];
    float lm = -1e30f;
    #pragma unroll
    for (int k = 0; k < 8; ++k) {
        tv[k] = g_topv[(size_t)row * NSUB + tid + k * 256];
        lm = fmaxf(lm, tv[k]);
    }
    sv[tid] = lm; s1[tid] = p.x; s2[tid] = p.y;
    if (tid == 0) ccnt = 0;
    __syncthreads();
    for (int s = 128; s > 0; s >>= 1) {
        if (tid < s) {
            s1[tid] += s1[tid + s];
            s2[tid] += s2[tid + s];
            sv[tid] = fmaxf(sv[tid], sv[tid + s]);
        }
        __syncthreads();
    }
    float M = sv[0], sum = s1[0], sumsq = s2[0];
    __syncthreads();

    float thr = M - MARGIN;
    #pragma unroll
    for (int k = 0; k < 8; ++k) {
        if (tv[k] >= thr) {
            int pos = atomicAdd(&ccnt, 1);
            if (pos < 64) clist[pos] = tid + k * 256;
        }
    }
    __syncthreads();
    int nc = min(ccnt, 64);

    // exact fp32 dots: 16 keys per candidate sub-block, 16 threads/key, coalesced
    int kg = tid >> 4;       // key within sub-block
    int lig = tid & 15;      // lane within key group
    float bv = -1e30f; int bi = 0x7fffffff;
    const float4* qp = (const float4*)(g_qn + (size_t)row * D_);
    for (int ci = 0; ci < nc; ++ci) {
        int n = clist[ci] * 16 + kg;
        const float4* kp = (const float4*)(keys + (size_t)n * D_);
        float a0 = 0.f;
        #pragma unroll
        for (int j = 0; j < 16; ++j) {
            float4 qa = qp[j * 16 + lig], kb = kp[j * 16 + lig];
            a0 += qa.x*kb.x + qa.y*kb.y + qa.z*kb.z + qa.w*kb.w;
        }
        a0 += __shfl_xor_sync(0xffffffffu, a0, 8);
        a0 += __shfl_xor_sync(0xffffffffu, a0, 4);
        a0 += __shfl_xor_sync(0xffffffffu, a0, 2);
        a0 += __shfl_xor_sync(0xffffffffu, a0, 1);
        if (lig == 0) {
            float s = a0 * g_kinv[n];
            if (s > bv || (s == bv && n < bi)) { bv = s; bi = n; }
        }
    }
    sv[tid] = (lig == 0) ? bv : -1e30f;
    si[tid] = (lig == 0) ? bi : 0x7fffffff;
    __syncthreads();
    for (int s = 128; s > 0; s >>= 1) {
        if (tid < s) {
            if (sv[tid + s] > sv[tid] ||
                (sv[tid + s] == sv[tid] && si[tid + s] < si[tid])) {
                sv[tid] = sv[tid + s]; si[tid] = si[tid + s];
            }
        }
        __syncthreads();
    }
    int best = si[0];

    const float4* vp = (const float4*)(values + (size_t)best * D_);
    float4* op = (float4*)(out + (size_t)row * D_);
    op[tid] = vp[tid];

    if (tid == 0)
        g_var[row] = (sumsq - sum * sum * (1.0f / N_)) * (1.0f / (N_ - 1));
}

__global__ void var_mean(float* __restrict__ out, int out_size) {
    __shared__ float sh[256];
    int tid = threadIdx.x;
    float a = 0.f;
    for (int i = tid; i < B_; i += 256) a += g_var[i];
    sh[tid] = a; __syncthreads();
    for (int s = 128; s > 0; s >>= 1) { if (tid < s) sh[tid] += sh[tid + s]; __syncthreads(); }
    if (tid == 0) {
        long long base = (long long)B_ * D_;
        if (out_size > base) out[base] = sh[0] * (1.0f / B_);
    }
}

// ------------------------- launch -------------------------
extern "C" void kernel_launch(void* const* d_in, const int* in_sizes, int n_in,
                              void* d_out, int out_size) {
    const float* q = (const float*)d_in[0];
    const float* k = (const float*)d_in[1];
    const float* v = (const float*)d_in[2];
    float* out = (float*)d_out;

    const int dyn = NSTAGE * STAGE_BYTES;   // 98304
    cudaFuncSetAttribute(sim_gemm, cudaFuncAttributeMaxDynamicSharedMemorySize, dyn);

    norm_rows_q<<<B_, 256>>>(q);
    norm_rows_k<<<N_, 256>>>(k);
    dim3 g(B_ / BM, N_ / BN);     // m fastest -> K-tile reuse through L2
    sim_gemm<<<g, 256, dyn>>>();
    finalize_rows<<<B_, 256>>>(k, v, out);
    var_mean<<<1, 256>>>(out, out_size);
}